// round 7
// baseline (speedup 1.0000x reference)
#include <cuda_runtime.h>
#include <math_constants.h>

// NNLoss: bidirectional 2-D NN loss via uniform-grid spatial binning.
// Kernel 1: per-(set,batch) block-local bin (count+scan+scatter in shared),
//           serpentine cell ordering.
// Kernel 2: warp-cooperative union-box ring search: all lanes of a warp scan
//           identical warp-uniform spans (LDS broadcast, no divergence).

namespace {
constexpr int   Bc   = 64;
constexpr int   Nc   = 2048;
constexpr int   NSB  = 2 * Bc;            // (set, batch) segments = 128
constexpr int   G    = 64;
constexpr int   G2   = G * G;             // 4096 cells
constexpr int   SST  = G2 + 8;            // starts stride (padded)
constexpr float EXT  = 6.0f;
constexpr float CELL = 2.0f * EXT / G;    // 0.1875
constexpr float INVC = (float)G / (2.0f * EXT);
constexpr int   TPB  = 256;
constexpr int   QCH  = Nc / TPB;          // 8 query chunks per (dir,b)
}

__device__ unsigned short g_start[NSB * SST];   // exclusive cell starts (+total)
__device__ float2         g_sorted[NSB * Nc];   // cell-sorted {x, y}

__device__ __forceinline__ int cell_of(float v) {
    int c = __float2int_rd((v + EXT) * INVC);
    return min(G - 1, max(0, c));
}
// serpentine cell id: odd rows reversed so consecutive cells stay adjacent
__device__ __forceinline__ int cell_id(int x, int y) {
    return y * G + ((y & 1) ? (G - 1 - x) : x);
}

// ---------------- Kernel 1: block-local binning ----------------
__global__ __launch_bounds__(TPB)
void bin_kernel(const float* __restrict__ preds,
                const float* __restrict__ targs,
                float* __restrict__ out)
{
    __shared__ unsigned int scnt[G2];      // counts -> scatter cursors
    __shared__ float2 pts[Nc];
    __shared__ unsigned int part[TPB];

    const int sb  = blockIdx.x;            // set*64 + b
    const int set = sb >> 6;
    const int b   = sb & (Bc - 1);
    if (sb == 0 && threadIdx.x == 0) out[0] = 0.0f;

    const float4* src = reinterpret_cast<const float4*>(set ? targs : preds)
                      + (size_t)b * Nc;
#pragma unroll
    for (int i = 0; i < Nc / TPB; ++i) {
        float4 p = src[threadIdx.x + i * TPB];
        pts[threadIdx.x + i * TPB] = make_float2(p.x, p.y);
    }
#pragma unroll
    for (int i = 0; i < G2 / TPB; ++i)
        scnt[threadIdx.x + i * TPB] = 0u;
    __syncthreads();

#pragma unroll
    for (int i = 0; i < Nc / TPB; ++i) {
        float2 p = pts[threadIdx.x + i * TPB];
        atomicAdd(&scnt[cell_id(cell_of(p.x), cell_of(p.y))], 1u);
    }
    __syncthreads();

    // block exclusive scan of 4096 counters
    unsigned int v[16], sum = 0;
    const int base = threadIdx.x * 16;
#pragma unroll
    for (int i = 0; i < 16; ++i) { v[i] = scnt[base + i]; sum += v[i]; }
    part[threadIdx.x] = sum;
    __syncthreads();
    for (int off = 1; off < TPB; off <<= 1) {
        unsigned int a = (threadIdx.x >= off) ? part[threadIdx.x - off] : 0u;
        __syncthreads();
        if (threadIdx.x >= off) part[threadIdx.x] += a;
        __syncthreads();
    }
    unsigned int run = threadIdx.x ? part[threadIdx.x - 1] : 0u;
    unsigned short* st = g_start + sb * SST;
#pragma unroll
    for (int i = 0; i < 16; ++i) {
        scnt[base + i] = run;                       // scatter cursor
        st[base + i]   = (unsigned short)run;
        run += v[i];
    }
    if (threadIdx.x == TPB - 1) st[G2] = (unsigned short)run;   // 2048
    __syncthreads();

    float2* dst = g_sorted + (size_t)sb * Nc;
#pragma unroll
    for (int i = 0; i < Nc / TPB; ++i) {
        float2 p = pts[threadIdx.x + i * TPB];
        unsigned int pos =
            atomicAdd(&scnt[cell_id(cell_of(p.x), cell_of(p.y))], 1u);
        dst[pos] = p;
    }
}

// ---------------- Kernel 2: warp-cooperative ring-search ----------------
__global__ __launch_bounds__(TPB)
void query_kernel(const float* __restrict__ subcoef, float* __restrict__ out)
{
    __shared__ float2 tile[Nc];                  // db points (cell-sorted)
    __shared__ unsigned short sst[G2 + 1];       // db cell starts
    __shared__ float red[TPB / 32];

    int bid = blockIdx.x;
    const int chunk = bid & (QCH - 1);  bid >>= 3;
    const int b     = bid & (Bc - 1);   bid >>= 6;
    const int dir   = bid;                       // 0: preds->targs, 1: targs->preds
    const int qsb = dir * Bc + b;                // query set (set0 = preds)
    const int dsb = (1 - dir) * Bc + b;          // db set

    for (int t = threadIdx.x; t < Nc; t += TPB)  tile[t] = g_sorted[(size_t)dsb * Nc + t];
    for (int t = threadIdx.x; t <= G2; t += TPB) sst[t]  = g_start[dsb * SST + t];
    __syncthreads();

    // queries = own set's sorted points -> warp lanes are cell-adjacent
    float2 q = g_sorted[(size_t)qsb * Nc + chunk * TPB + threadIdx.x];
    const float qx = q.x, qy = q.y;
    const int cx = cell_of(qx), cy = cell_of(qy);

    // warp-union cell bounding box (uniform across lanes)
    const int minx = __reduce_min_sync(0xffffffffu, cx);
    const int maxx = __reduce_max_sync(0xffffffffu, cx);
    const int miny = __reduce_min_sync(0xffffffffu, cy);
    const int maxy = __reduce_max_sync(0xffffffffu, cy);

    float best = CUDART_INF_F;
    int   bj   = 0;

    // scan cells [xa..xb] of row y (warp-uniform); serpentine keeps it one span
    auto row_span = [&](int y, int xa, int xb) {
        int base = y * G;
        int lo, hi;
        if (y & 1) { lo = base + (G - 1 - xb); hi = base + (G - 1 - xa); }
        else       { lo = base + xa;           hi = base + xb;           }
        int j = sst[lo], je = sst[hi + 1];
        for (; j + 1 < je; j += 2) {
            float2 t0 = tile[j];                 // LDS broadcast
            float2 t1 = tile[j + 1];
            float dx0 = t0.x - qx, dy0 = t0.y - qy;
            float dx1 = t1.x - qx, dy1 = t1.y - qy;
            float s0 = fmaf(dx0, dx0, dy0 * dy0);
            float s1 = fmaf(dx1, dx1, dy1 * dy1);
            if (s0 < best) { best = s0; bj = j; }
            if (s1 < best) { best = s1; bj = j + 1; }
        }
        if (j < je) {
            float2 t0 = tile[j];
            float dx0 = t0.x - qx, dy0 = t0.y - qy;
            float s0 = fmaf(dx0, dx0, dy0 * dy0);
            if (s0 < best) { best = s0; bj = j; }
        }
    };

    // k=1: union box grown by 1
    int xa = max(minx - 1, 0), xb = min(maxx + 1, G - 1);
    int ya = max(miny - 1, 0), yb = min(maxy + 1, G - 1);
    for (int y = ya; y <= yb; ++y) row_span(y, xa, xb);

    // expand perimeter; unscanned cells are Chebyshev >= k from every lane's
    // cell, so their points are at distance >= (k-1)*CELL
    for (int k = 2; k < 2 * G; ++k) {
        float bd = (float)(k - 1) * CELL;
        if (__all_sync(0xffffffffu, best <= bd * bd)) break;
        int nxa = max(minx - k, 0), nxb = min(maxx + k, G - 1);
        int nya = max(miny - k, 0), nyb = min(maxy + k, G - 1);
        if (miny - k >= 0) row_span(nya, nxa, nxb);     // new top row
        if (maxy + k < G)  row_span(nyb, nxa, nxb);     // new bottom row
        if (minx - k >= 0)                              // new left column
            for (int y = ya; y <= yb; ++y) row_span(y, nxa, nxa);
        if (maxx + k < G)                               // new right column
            for (int y = ya; y <= yb; ++y) row_span(y, nxb, nxb);
        xa = nxa; xb = nxb; ya = nya; yb = nyb;
    }

    float2 w = tile[bj];
    const float cA = dir ? 1.0f : subcoef[0];
    const float cB = dir ? 1.0f : subcoef[1];
    float contrib = fabsf(qx - w.x) * cA + fabsf(qy - w.y) * cB;

#pragma unroll
    for (int o = 16; o > 0; o >>= 1)
        contrib += __shfl_down_sync(0xffffffffu, contrib, o);
    if ((threadIdx.x & 31) == 0) red[threadIdx.x >> 5] = contrib;
    __syncthreads();
    if (threadIdx.x < 32) {
        float v = (threadIdx.x < TPB / 32) ? red[threadIdx.x] : 0.0f;
#pragma unroll
        for (int o = 4; o > 0; o >>= 1)
            v += __shfl_down_sync(0x000000ffu, v, o);
        if (threadIdx.x == 0) atomicAdd(out, v);
    }
}

extern "C" void kernel_launch(void* const* d_in, const int* in_sizes, int n_in,
                              void* d_out, int out_size)
{
    const float* preds   = (const float*)d_in[0];
    const float* targs   = (const float*)d_in[1];
    const float* subcoef = (const float*)d_in[2];
    float* out = (float*)d_out;

    bin_kernel  <<<NSB, TPB>>>(preds, targs, out);          // 128 blocks
    query_kernel<<<2 * Bc * QCH, TPB>>>(subcoef, out);      // 1024 blocks
}

// round 9
// speedup vs baseline: 1.2862x; 1.2862x over previous
#include <cuda_runtime.h>
#include <math_constants.h>

// NNLoss: bidirectional 2-D NN loss via uniform-grid spatial binning.
// Kernel 1: per-(set,batch) block-local bin (count+scan+scatter in shared).
// Kernel 2: per-lane 3x3-box scan (uniform 3-row structure, unroll-4,
//           packed bits|index argmin) + rare per-lane ring expansion.

namespace {
constexpr int   Bc   = 64;
constexpr int   Nc   = 2048;
constexpr int   NSB  = 2 * Bc;            // (set, batch) segments = 128
constexpr int   G    = 64;
constexpr int   G2   = G * G;             // 4096 cells
constexpr int   SST  = G2 + 8;            // starts stride (padded)
constexpr float EXT  = 6.0f;
constexpr float CELL = 2.0f * EXT / G;    // 0.1875
constexpr float INVC = (float)G / (2.0f * EXT);
constexpr int   TPB  = 256;
constexpr int   QCH  = Nc / TPB;          // 8 query chunks per (dir,b)
constexpr unsigned IDXMASK = 2047u;       // low 11 bits carry tile index
// sentinel: +INF in high bits, index field saturated. Unsigned-comparable,
// extracts to +INF (so "empty box" correctly forces ring expansion).
constexpr unsigned SENTINEL = 0x7F800000u | IDXMASK;
}

__device__ unsigned short g_start[NSB * SST];   // exclusive cell starts (+total)
__device__ float2         g_sorted[NSB * Nc];   // cell-sorted {x, y}

__device__ __forceinline__ int cell_of(float v) {
    int c = __float2int_rd((v + EXT) * INVC);
    return min(G - 1, max(0, c));
}

// ---------------- Kernel 1: block-local binning ----------------
__global__ __launch_bounds__(TPB)
void bin_kernel(const float* __restrict__ preds,
                const float* __restrict__ targs,
                float* __restrict__ out)
{
    __shared__ unsigned int scnt[G2];      // counts -> scatter cursors
    __shared__ float2 pts[Nc];
    __shared__ unsigned int part[TPB];

    const int sb  = blockIdx.x;            // set*64 + b
    const int set = sb >> 6;
    const int b   = sb & (Bc - 1);
    if (sb == 0 && threadIdx.x == 0) out[0] = 0.0f;

    const float4* src = reinterpret_cast<const float4*>(set ? targs : preds)
                      + (size_t)b * Nc;
#pragma unroll
    for (int i = 0; i < Nc / TPB; ++i) {
        float4 p = src[threadIdx.x + i * TPB];
        pts[threadIdx.x + i * TPB] = make_float2(p.x, p.y);
    }
#pragma unroll
    for (int i = 0; i < G2 / TPB; ++i)
        scnt[threadIdx.x + i * TPB] = 0u;
    __syncthreads();

#pragma unroll
    for (int i = 0; i < Nc / TPB; ++i) {
        float2 p = pts[threadIdx.x + i * TPB];
        atomicAdd(&scnt[cell_of(p.y) * G + cell_of(p.x)], 1u);
    }
    __syncthreads();

    // block exclusive scan of 4096 counters
    unsigned int v[16], sum = 0;
    const int base = threadIdx.x * 16;
#pragma unroll
    for (int i = 0; i < 16; ++i) { v[i] = scnt[base + i]; sum += v[i]; }
    part[threadIdx.x] = sum;
    __syncthreads();
    for (int off = 1; off < TPB; off <<= 1) {
        unsigned int a = (threadIdx.x >= off) ? part[threadIdx.x - off] : 0u;
        __syncthreads();
        if (threadIdx.x >= off) part[threadIdx.x] += a;
        __syncthreads();
    }
    unsigned int run = threadIdx.x ? part[threadIdx.x - 1] : 0u;
    unsigned short* st = g_start + sb * SST;
#pragma unroll
    for (int i = 0; i < 16; ++i) {
        scnt[base + i] = run;                       // scatter cursor
        st[base + i]   = (unsigned short)run;
        run += v[i];
    }
    if (threadIdx.x == TPB - 1) st[G2] = (unsigned short)run;   // 2048
    __syncthreads();

    float2* dst = g_sorted + (size_t)sb * Nc;
#pragma unroll
    for (int i = 0; i < Nc / TPB; ++i) {
        float2 p = pts[threadIdx.x + i * TPB];
        unsigned int pos = atomicAdd(&scnt[cell_of(p.y) * G + cell_of(p.x)], 1u);
        dst[pos] = p;
    }
}

// ---------------- Kernel 2: per-lane box scan + rare expansion ----------------
__global__ __launch_bounds__(TPB)
void query_kernel(const float* __restrict__ subcoef, float* __restrict__ out)
{
    __shared__ float2 tile[Nc];                  // db points (cell-sorted)
    __shared__ unsigned short sst[G2 + 1];       // db cell starts
    __shared__ float red[TPB / 32];

    int bid = blockIdx.x;
    const int chunk = bid & (QCH - 1);  bid >>= 3;
    const int b     = bid & (Bc - 1);   bid >>= 6;
    const int dir   = bid;                       // 0: preds->targs, 1: targs->preds
    const int qsb = dir * Bc + b;                // query set (set0 = preds)
    const int dsb = (1 - dir) * Bc + b;          // db set

    for (int t = threadIdx.x; t < Nc; t += TPB)  tile[t] = g_sorted[(size_t)dsb * Nc + t];
    for (int t = threadIdx.x; t <= G2; t += TPB) sst[t]  = g_start[dsb * SST + t];
    __syncthreads();

    // queries = own set's sorted points (order-invariant loss; cell-coherent lanes)
    float2 q = g_sorted[(size_t)qsb * Nc + chunk * TPB + threadIdx.x];
    const float qx = q.x, qy = q.y;
    const int cx = cell_of(qx), cy = cell_of(qy);

    // packed running argmin: high 21 bits = truncated float bits of d^2,
    // low 11 bits = tile index. Monotone since d^2 >= 0 (bits positive).
    unsigned mn = SENTINEL;

    auto eval = [&](int j) {
        float2 t = tile[j];
        float dx = t.x - qx, dy = t.y - qy;
        float s = fmaf(dx, dx, dy * dy);
        unsigned pk = (__float_as_uint(s) & ~IDXMASK) | (unsigned)j;
        mn = min(mn, pk);
    };
    auto scan = [&](int j, int je) {
        for (; j + 3 < je; j += 4) { eval(j); eval(j + 1); eval(j + 2); eval(j + 3); }
        for (; j < je; ++j) eval(j);
    };

    // fast path: 3x3 box, three contiguous row spans (uniform structure)
    const int xa = max(cx - 1, 0), xb = min(cx + 1, G - 1);
    const int ya = max(cy - 1, 0), yb = min(cy + 1, G - 1);
    for (int y = ya; y <= yb; ++y)
        scan(sst[y * G + xa], sst[y * G + xb + 1]);

    // exit bound: any point outside the 3x3 box is >= CELL away.
    // Empty box -> best = +INF -> expansion path taken.
    float best = __uint_as_float(mn & ~IDXMASK);
    if (__any_sync(0xffffffffu, best > CELL * CELL)) {
        if (best > CELL * CELL) {
            // per-lane ring expansion; unscanned cells (Chebyshev >= k)
            // hold points at distance >= (k-1)*CELL
            for (int k = 2; k < G; ++k) {
                float bd = (float)(k - 1) * CELL;
                if (best <= bd * bd) break;
                const int exa = max(cx - k, 0), exb = min(cx + k, G - 1);
                const int eya = max(cy - k, 0), eyb = min(cy + k, G - 1);
                for (int y = eya; y <= eyb; ++y) {
                    if (y == cy - k || y == cy + k) {
                        scan(sst[y * G + exa], sst[y * G + exb + 1]);
                    } else {
                        if (cx - k >= 0) {
                            int cc = y * G + cx - k;
                            scan(sst[cc], sst[cc + 1]);
                        }
                        if (cx + k < G) {
                            int cc = y * G + cx + k;
                            scan(sst[cc], sst[cc + 1]);
                        }
                    }
                }
                best = __uint_as_float(mn & ~IDXMASK);
            }
        }
    }

    float2 w = tile[mn & IDXMASK];
    const float cA = dir ? 1.0f : subcoef[0];
    const float cB = dir ? 1.0f : subcoef[1];
    float contrib = fabsf(qx - w.x) * cA + fabsf(qy - w.y) * cB;

#pragma unroll
    for (int o = 16; o > 0; o >>= 1)
        contrib += __shfl_down_sync(0xffffffffu, contrib, o);
    if ((threadIdx.x & 31) == 0) red[threadIdx.x >> 5] = contrib;
    __syncthreads();
    if (threadIdx.x < 32) {
        float v = (threadIdx.x < TPB / 32) ? red[threadIdx.x] : 0.0f;
#pragma unroll
        for (int o = 4; o > 0; o >>= 1)
            v += __shfl_down_sync(0x000000ffu, v, o);
        if (threadIdx.x == 0) atomicAdd(out, v);
    }
}

extern "C" void kernel_launch(void* const* d_in, const int* in_sizes, int n_in,
                              void* d_out, int out_size)
{
    const float* preds   = (const float*)d_in[0];
    const float* targs   = (const float*)d_in[1];
    const float* subcoef = (const float*)d_in[2];
    float* out = (float*)d_out;

    bin_kernel  <<<NSB, TPB>>>(preds, targs, out);          // 128 blocks
    query_kernel<<<2 * Bc * QCH, TPB>>>(subcoef, out);      // 1024 blocks
}